// round 14
// baseline (speedup 1.0000x reference)
#include <cuda_runtime.h>
#include <cuda_bf16.h>
#include <math.h>
#include <cstdint>

#define Bc   2
#define LQc  1024
#define LKVc 4096
#define Hc   1024
#define NHc  16
#define HDc  64
#define K3   (3 * Hc)          // augmented K = 3072

// ---- scratch (static device globals; no allocations allowed) ----
__device__ float g_y[(size_t)Bc * LQc * Hc];

// augmented split-bf16 GEMM operands
__device__ __nv_bfloat16 g_hs3 [(size_t)Bc * LQc  * K3];
__device__ __nv_bfloat16 g_ehs3[(size_t)Bc * LKVc * K3];
__device__ __nv_bfloat16 g_ctx3[(size_t)Bc * LQc  * K3];
__device__ __nv_bfloat16 g_qw3 [(size_t)Hc * K3];
__device__ __nv_bfloat16 g_kw3 [(size_t)Hc * K3];
__device__ __nv_bfloat16 g_vw3 [(size_t)Hc * K3];
__device__ __nv_bfloat16 g_ow3 [(size_t)Hc * K3];

// split outputs of Q/K/V projections (consumed by attention)
__device__ __nv_bfloat16 g_Qhi[(size_t)Bc * LQc  * Hc];
__device__ __nv_bfloat16 g_Qlo[(size_t)Bc * LQc  * Hc];
__device__ __nv_bfloat16 g_Khi[(size_t)Bc * LKVc * Hc];
__device__ __nv_bfloat16 g_Klo[(size_t)Bc * LKVc * Hc];
__device__ __nv_bfloat16 g_Vhi[(size_t)Bc * LKVc * Hc];

// ===========================================================================
// helpers
// ===========================================================================
__device__ __forceinline__ uint32_t smem_u32(const void* p) {
    uint32_t a;
    asm("{ .reg .u64 t; cvta.to.shared.u64 t, %1; cvt.u32.u64 %0, t; }"
        : "=r"(a) : "l"(p));
    return a;
}
__device__ __forceinline__ void cp16(uint32_t dst, const void* src) {
    asm volatile("cp.async.cg.shared.global [%0], [%1], 16;" :: "r"(dst), "l"(src));
}
__device__ __forceinline__ void cp_commit() {
    asm volatile("cp.async.commit_group;" ::: "memory");
}
template <int N> __device__ __forceinline__ void cp_wait() {
    asm volatile("cp.async.wait_group %0;" :: "n"(N) : "memory");
}
__device__ __forceinline__ void ldm_x4(uint32_t& r0, uint32_t& r1,
                                       uint32_t& r2, uint32_t& r3, uint32_t a) {
    asm volatile("ldmatrix.sync.aligned.m8n8.x4.shared.b16 {%0,%1,%2,%3}, [%4];"
                 : "=r"(r0), "=r"(r1), "=r"(r2), "=r"(r3) : "r"(a));
}
__device__ __forceinline__ void ldm_x4t(uint32_t& r0, uint32_t& r1,
                                        uint32_t& r2, uint32_t& r3, uint32_t a) {
    asm volatile("ldmatrix.sync.aligned.m8n8.x4.trans.shared.b16 {%0,%1,%2,%3}, [%4];"
                 : "=r"(r0), "=r"(r1), "=r"(r2), "=r"(r3) : "r"(a));
}
__device__ __forceinline__ void mma16816(float* c, uint32_t a0, uint32_t a1,
                                         uint32_t a2, uint32_t a3,
                                         uint32_t b0, uint32_t b1) {
    asm volatile(
        "mma.sync.aligned.m16n8k16.row.col.f32.bf16.bf16.f32 "
        "{%0,%1,%2,%3}, {%4,%5,%6,%7}, {%8,%9}, {%0,%1,%2,%3};"
        : "+f"(c[0]), "+f"(c[1]), "+f"(c[2]), "+f"(c[3])
        : "r"(a0), "r"(a1), "r"(a2), "r"(a3), "r"(b0), "r"(b1));
}
__device__ __forceinline__ uint32_t pack2(float lo, float hi) {
    uint32_t r;
    asm("cvt.rn.bf16x2.f32 %0, %2, %1;" : "=r"(r) : "f"(lo), "f"(hi));
    return r;
}
__device__ __forceinline__ uint32_t packbf2(float v0, float v1) {
    __nv_bfloat16 h0 = __float2bfloat16(v0);
    __nv_bfloat16 h1 = __float2bfloat16(v1);
    return (uint32_t)__bfloat16_as_ushort(h0)
         | ((uint32_t)__bfloat16_as_ushort(h1) << 16);
}

// ===========================================================================
// split fp32 row [R,1024] -> bf16 [R,3072]
//   mode 0 (activation): [hi | lo | hi]   mode 1 (weight): [hi | hi | lo]
// ===========================================================================
__global__ __launch_bounds__(256) void split3(
    const float* __restrict__ x, __nv_bfloat16* __restrict__ out3,
    int n4, int mode)
{
    int i = blockIdx.x * 256 + threadIdx.x;
    if (i >= n4) return;
    int row  = i >> 8;
    int col4 = i & 255;
    float4 v = reinterpret_cast<const float4*>(x)[i];
    __nv_bfloat16 h0 = __float2bfloat16(v.x), h1 = __float2bfloat16(v.y);
    __nv_bfloat16 h2 = __float2bfloat16(v.z), h3 = __float2bfloat16(v.w);
    __nv_bfloat16 l0 = __float2bfloat16(v.x - __bfloat162float(h0));
    __nv_bfloat16 l1 = __float2bfloat16(v.y - __bfloat162float(h1));
    __nv_bfloat16 l2 = __float2bfloat16(v.z - __bfloat162float(h2));
    __nv_bfloat16 l3 = __float2bfloat16(v.w - __bfloat162float(h3));
    uint2 hp, lp;
    hp.x = (uint32_t)__bfloat16_as_ushort(h0) | ((uint32_t)__bfloat16_as_ushort(h1) << 16);
    hp.y = (uint32_t)__bfloat16_as_ushort(h2) | ((uint32_t)__bfloat16_as_ushort(h3) << 16);
    lp.x = (uint32_t)__bfloat16_as_ushort(l0) | ((uint32_t)__bfloat16_as_ushort(l1) << 16);
    lp.y = (uint32_t)__bfloat16_as_ushort(l2) | ((uint32_t)__bfloat16_as_ushort(l3) << 16);
    uint2* o = reinterpret_cast<uint2*>(out3 + (size_t)row * K3) + col4;
    if (mode == 0) { o[0] = hp; o[256] = lp; o[512] = hp; }
    else           { o[0] = hp; o[256] = hp; o[512] = lp; }
}

// ===========================================================================
// bf16 mma.sync GEMM, BK=64 chunks, 3-stage single-sync pipeline.
//   NCH=48: full augmented K=3072 (split precision)
//   NCH=16: plain bf16 over first K=1024 (hi x hi only)
// outmode 0: fp32 C = acc + bias (+ res); 1: bf16 hi/lo; 2: bf16 hi only
// ===========================================================================
#define BKc     64
#define GROWB   144                  // bytes per smem row (64 bf16 + 8 pad)
#define ATILEB  (128 * GROWB)        // 18432
#define STAGEB2 (2 * ATILEB)         // 36864
#define GSMEM   (3 * STAGEB2)        // 110592

template <int NCH>
__global__ __launch_bounds__(256) void gemm_mma(
    const __nv_bfloat16* __restrict__ A3, const __nv_bfloat16* __restrict__ W3,
    const float* __restrict__ bias, const float* __restrict__ res,
    float* __restrict__ Cf, __nv_bfloat16* __restrict__ Chi,
    __nv_bfloat16* __restrict__ Clo, int outmode)
{
    extern __shared__ char smem[];
    const uint32_t sbase = smem_u32(smem);
    const int tid  = threadIdx.x;
    const int lane = tid & 31;
    const int wid  = tid >> 5;
    const int wm   = wid & 3;
    const int wn   = wid >> 2;
    const int n0   = blockIdx.x * 128;
    const int m0   = blockIdx.y * 128;

    const int lrow = tid >> 1;          // 0..127
    const int h    = tid & 1;           // half of a 128B row

    const __nv_bfloat16* Arow = A3 + (size_t)(m0 + lrow) * K3 + h * 32;
    const __nv_bfloat16* Wrow = W3 + (size_t)(n0 + lrow) * K3 + h * 32;
    const uint32_t dstA = sbase + lrow * GROWB + h * 64;
    const uint32_t dstW = sbase + ATILEB + lrow * GROWB + h * 64;

    #define LOAD_CHUNK(c, s)                                                  \
        do {                                                                  \
            const __nv_bfloat16* ap = Arow + (c) * BKc;                       \
            const __nv_bfloat16* wp = Wrow + (c) * BKc;                       \
            uint32_t so = (s) * STAGEB2;                                      \
            cp16(dstA + so,      ap);                                         \
            cp16(dstA + so + 16, ap + 8);                                     \
            cp16(dstA + so + 32, ap + 16);                                    \
            cp16(dstA + so + 48, ap + 24);                                    \
            cp16(dstW + so,      wp);                                         \
            cp16(dstW + so + 16, wp + 8);                                     \
            cp16(dstW + so + 32, wp + 16);                                    \
            cp16(dstW + so + 48, wp + 24);                                    \
            cp_commit();                                                      \
        } while (0)

    LOAD_CHUNK(0, 0);
    LOAD_CHUNK(1, 1);

    float acc[2][8][4];
    #pragma unroll
    for (int i = 0; i < 2; i++)
        #pragma unroll
        for (int j = 0; j < 8; j++)
            #pragma unroll
            for (int r = 0; r < 4; r++) acc[i][j][r] = 0.f;

    const int aRow = wm * 32 + (lane & 15);
    const int aKof = (lane >> 4) * 8;
    const int bRow = wn * 64 + ((lane >> 4) * 8) + (lane & 7);
    const int bKof = ((lane >> 3) & 1) * 8;

    for (int c = 0; c < NCH; ++c) {
        if (c < NCH - 1) cp_wait<1>(); else cp_wait<0>();
        __syncthreads();
        // refill stage consumed LAST iteration (safe: all warps past barrier)
        if (c + 2 < NCH) LOAD_CHUNK(c + 2, (c + 2) % 3);

        const uint32_t sa = sbase + (c % 3) * STAGEB2;
        const uint32_t sw = sa + ATILEB;

        #pragma unroll
        for (int kk = 0; kk < 4; ++kk) {            // four k16 steps (BK=64)
            const int kb = kk * 16;
            uint32_t a[2][4];
            #pragma unroll
            for (int i = 0; i < 2; i++) {
                uint32_t addr = sa + (uint32_t)(aRow + i * 16) * GROWB
                              + (uint32_t)(kb + aKof) * 2;
                ldm_x4(a[i][0], a[i][1], a[i][2], a[i][3], addr);
            }
            #pragma unroll
            for (int jj = 0; jj < 4; ++jj) {
                uint32_t b0, b1, b2, b3;
                uint32_t addr = sw + (uint32_t)(bRow + jj * 16) * GROWB
                              + (uint32_t)(kb + bKof) * 2;
                ldm_x4(b0, b1, b2, b3, addr);
                #pragma unroll
                for (int i = 0; i < 2; i++) {
                    mma16816(acc[i][jj * 2 + 0], a[i][0], a[i][1], a[i][2], a[i][3], b0, b1);
                    mma16816(acc[i][jj * 2 + 1], a[i][0], a[i][1], a[i][2], a[i][3], b2, b3);
                }
            }
        }
    }

    const int colBase = n0 + wn * 64 + (lane & 3) * 2;
    const int rowBase = m0 + wm * 32 + (lane >> 2);
    #pragma unroll
    for (int i = 0; i < 2; i++) {
        #pragma unroll
        for (int j = 0; j < 8; j++) {
            const int col = colBase + j * 8;
            #pragma unroll
            for (int hh = 0; hh < 2; hh++) {
                const int row = rowBase + i * 16 + hh * 8;
                float v0 = acc[i][j][hh * 2 + 0] + bias[col];
                float v1 = acc[i][j][hh * 2 + 1] + bias[col + 1];
                if (outmode == 0) {
                    if (res) {
                        const float* rp = res + (size_t)row * Hc + col;
                        v0 += rp[0]; v1 += rp[1];
                    }
                    *reinterpret_cast<float2*>(Cf + (size_t)row * Hc + col)
                        = make_float2(v0, v1);
                } else {
                    __nv_bfloat16 h0 = __float2bfloat16(v0);
                    __nv_bfloat16 h1 = __float2bfloat16(v1);
                    uint32_t hp = (uint32_t)__bfloat16_as_ushort(h0)
                                | ((uint32_t)__bfloat16_as_ushort(h1) << 16);
                    *reinterpret_cast<uint32_t*>(
                        (__nv_bfloat16*)Chi + (size_t)row * Hc + col) = hp;
                    if (outmode == 1) {
                        __nv_bfloat16 l0 = __float2bfloat16(v0 - __bfloat162float(h0));
                        __nv_bfloat16 l1 = __float2bfloat16(v1 - __bfloat162float(h1));
                        uint32_t lp = (uint32_t)__bfloat16_as_ushort(l0)
                                    | ((uint32_t)__bfloat16_as_ushort(l1) << 16);
                        *reinterpret_cast<uint32_t*>(
                            (__nv_bfloat16*)Clo + (size_t)row * Hc + col) = lp;
                    }
                }
            }
        }
    }
}

// ===========================================================================
// Tensor-core flash attention, KT=64, 2 CTAs/SM, 3-stage single-sync.
// Stage 2 is aliased into the Q staging area (Q lives in registers after the
// one-time fragment preload). Q frags register-resident; no online max.
// ctx written directly as split bf16 [hi|lo|hi] rows of ctx3.
// ===========================================================================
#define KT    64
#define NTILE (LKVc / KT)        // 64
#define QSTR  272
#define KSTR  272
#define VSTR  144
#define QB    (128 * QSTR)       // 34816
#define SV    (KT * KSTR)        // 17408
#define SMK   (SV + KT * VSTR)   // 26624
#define STG   (SMK + 256)        // 26880  (<= QB, so stage 2 fits in QB)
#define ASMEM (QB + 2 * STG)     // 88576

__global__ __launch_bounds__(256, 2) void attn_mma(
    const __nv_bfloat16* __restrict__ Qhi, const __nv_bfloat16* __restrict__ Qlo,
    const __nv_bfloat16* __restrict__ Khi, const __nv_bfloat16* __restrict__ Klo,
    const __nv_bfloat16* __restrict__ Vhi, const int* __restrict__ mask,
    float* __restrict__ scores, __nv_bfloat16* __restrict__ ctx3)
{
    extern __shared__ char smem[];
    const uint32_t sbase = smem_u32(smem);
    const int tid  = threadIdx.x;
    const int lane = tid & 31;
    const int wid  = tid >> 5;
    const int h    = blockIdx.y;
    const int b    = blockIdx.z;
    const int q0   = blockIdx.x * 128;

    // stage offsets: 0 -> QB, 1 -> QB+STG, 2 -> 0 (aliases Q area)
    #define STOFF(s) ((s) == 2 ? 0u : (uint32_t)(QB + (s) * STG))

    // ---- Q load (hi|lo interleaved rows) ----
    {
        const __nv_bfloat16* QH = Qhi + ((size_t)(b * LQc + q0)) * Hc + h * HDc;
        const __nv_bfloat16* QL = Qlo + ((size_t)(b * LQc + q0)) * Hc + h * HDc;
        #pragma unroll
        for (int k = 0; k < 8; ++k) {
            int i = tid + k * 256;
            int r = i >> 4, u = i & 15;
            const __nv_bfloat16* src = (u < 8) ? (QH + (size_t)r * Hc + u * 8)
                                               : (QL + (size_t)r * Hc + (u - 8) * 8);
            cp16(sbase + r * QSTR + u * 16, src);
        }
        cp_commit();
    }

    const __nv_bfloat16* KH = Khi + ((size_t)b * LKVc) * Hc + h * HDc;
    const __nv_bfloat16* KL = Klo + ((size_t)b * LKVc) * Hc + h * HDc;
    const __nv_bfloat16* VH = Vhi + ((size_t)b * LKVc) * Hc + h * HDc;
    const int* MS = mask + b * LKVc;

    #define LOAD_TILE(t, soff)                                                \
        do {                                                                  \
            uint32_t sb = sbase + (soff);                                     \
            int kv0 = (t) * KT;                                               \
            _Pragma("unroll")                                                 \
            for (int k = 0; k < 4; ++k) {                                     \
                int i = tid + k * 256;                                        \
                int r = i >> 4, u = i & 15;                                   \
                const __nv_bfloat16* src =                                    \
                    (u < 8) ? (KH + (size_t)(kv0 + r) * Hc + u * 8)           \
                            : (KL + (size_t)(kv0 + r) * Hc + (u - 8) * 8);    \
                cp16(sb + r * KSTR + u * 16, src);                            \
            }                                                                 \
            _Pragma("unroll")                                                 \
            for (int k = 0; k < 2; ++k) {                                     \
                int i = tid + k * 256;                                        \
                int r = i >> 3, u = i & 7;                                    \
                cp16(sb + SV + r * VSTR + u * 16,                             \
                     VH + (size_t)(kv0 + r) * Hc + u * 8);                    \
            }                                                                 \
            if (tid < 16) cp16(sb + SMK + tid * 16, MS + kv0 + tid * 4);      \
            cp_commit();                                                      \
        } while (0)

    LOAD_TILE(0, STOFF(0));
    LOAD_TILE(1, STOFF(1));

    const int wr = wid * 16;
    const int r0 = lane >> 2;
    const int c2 = (lane & 3) * 2;

    float l[2] = {0.f, 0.f};
    float ctxa[8][4];
    #pragma unroll
    for (int nf = 0; nf < 8; ++nf)
        #pragma unroll
        for (int r = 0; r < 4; ++r) ctxa[nf][r] = 0.f;

    float* sc0 = scores + ((size_t)(b * NHc + h) * LQc + q0 + wr + r0) * LKVc;
    float* sc1 = sc0 + 8 * (size_t)LKVc;

    const uint32_t aOff = (uint32_t)(wr + (lane & 15)) * QSTR + ((lane >> 4) * 16);
    const uint32_t bRowO = (uint32_t)(((lane >> 4) * 8) + (lane & 7)) * KSTR
                         + (((lane >> 3) & 1) * 16);
    const uint32_t vOff = (uint32_t)(lane & 15) * VSTR + ((lane >> 4) * 16);

    // ---- preload Q fragments (loop-invariant): qf[0..3]=hi, qf[4..7]=lo ----
    cp_wait<2>();
    __syncthreads();
    uint32_t qf[8][4];
    #pragma unroll
    for (int i = 0; i < 8; ++i)
        ldm_x4(qf[i][0], qf[i][1], qf[i][2], qf[i][3], sbase + aOff + i * 32);

    for (int t = 0; t < NTILE; ++t) {
        if (t < NTILE - 1) cp_wait<1>(); else cp_wait<0>();
        __syncthreads();
        // refill stage consumed last iteration (iter 0 writes stage 2 = Q area,
        // safe: Q frags extracted before the barrier above)
        if (t + 2 < NTILE) LOAD_TILE(t + 2, STOFF((t + 2) % 3));

        const uint32_t soff = STOFF(t % 3);
        const uint32_t kb_ = sbase + soff;
        const uint32_t vb_ = kb_ + SV;
        const int* mrow = (const int*)(smem + soff + SMK);
        const int kv0 = t * KT;

        // ---- S = Qaug Kaug^T (each B frag loaded exactly once) ----
        float sa[8][4];
        #pragma unroll
        for (int nf = 0; nf < 8; ++nf)
            #pragma unroll
            for (int r = 0; r < 4; ++r) sa[nf][r] = 0.f;

        #pragma unroll
        for (int nn = 0; nn < 4; ++nn) {
            uint32_t bf_[8][4];
            #pragma unroll
            for (int bo = 0; bo < 8; ++bo)
                ldm_x4(bf_[bo][0], bf_[bo][1], bf_[bo][2], bf_[bo][3],
                       kb_ + (uint32_t)(nn * 16) * KSTR + bRowO + bo * 32);
            #pragma unroll
            for (int kk = 0; kk < 4; ++kk) {
                mma16816(sa[nn*2+0], qf[kk][0], qf[kk][1], qf[kk][2], qf[kk][3],
                         bf_[kk][0], bf_[kk][1]);
                mma16816(sa[nn*2+1], qf[kk][0], qf[kk][1], qf[kk][2], qf[kk][3],
                         bf_[kk][2], bf_[kk][3]);
                mma16816(sa[nn*2+0], qf[kk][0], qf[kk][1], qf[kk][2], qf[kk][3],
                         bf_[kk+4][0], bf_[kk+4][1]);
                mma16816(sa[nn*2+1], qf[kk][0], qf[kk][1], qf[kk][2], qf[kk][3],
                         bf_[kk+4][2], bf_[kk+4][3]);
                mma16816(sa[nn*2+0], qf[kk+4][0], qf[kk+4][1], qf[kk+4][2], qf[kk+4][3],
                         bf_[kk][0], bf_[kk][1]);
                mma16816(sa[nn*2+1], qf[kk+4][0], qf[kk+4][1], qf[kk+4][2], qf[kk+4][3],
                         bf_[kk][2], bf_[kk][3]);
            }
        }

        // ---- scale + mask + scores write ----
        #pragma unroll
        for (int nf = 0; nf < 8; ++nf) {
            const int col = nf * 8 + c2;
            const bool ok0 = mrow[col] != 0;
            const bool ok1 = mrow[col + 1] != 0;
            sa[nf][0] = ok0 ? sa[nf][0] * 0.125f : -INFINITY;
            sa[nf][1] = ok1 ? sa[nf][1] * 0.125f : -INFINITY;
            sa[nf][2] = ok0 ? sa[nf][2] * 0.125f : -INFINITY;
            sa[nf][3] = ok1 ? sa[nf][3] * 0.125f : -INFINITY;
            *reinterpret_cast<float2*>(sc0 + kv0 + col) = make_float2(sa[nf][0], sa[nf][1]);
            *reinterpret_cast<float2*>(sc1 + kv0 + col) = make_float2(sa[nf][2], sa[nf][3]);
        }

        // ---- P = exp(s) (no max shift), pack to A-frags, accumulate l ----
        uint32_t pf[4][4];
        float ls0 = 0.f, ls1 = 0.f;
        #pragma unroll
        for (int kk = 0; kk < 4; ++kk) {
            float p00 = __expf(sa[2 * kk][0]);
            float p01 = __expf(sa[2 * kk][1]);
            float p10 = __expf(sa[2 * kk][2]);
            float p11 = __expf(sa[2 * kk][3]);
            float q00 = __expf(sa[2 * kk + 1][0]);
            float q01 = __expf(sa[2 * kk + 1][1]);
            float q10 = __expf(sa[2 * kk + 1][2]);
            float q11 = __expf(sa[2 * kk + 1][3]);
            ls0 += (p00 + p01) + (q00 + q01);
            ls1 += (p10 + p11) + (q10 + q11);
            pf[kk][0] = pack2(p00, p01);
            pf[kk][1] = pack2(p10, p11);
            pf[kk][2] = pack2(q00, q01);
            pf[kk][3] = pack2(q10, q11);
        }
        l[0] += ls0;
        l[1] += ls1;

        // ---- ctx += P V ----
        #pragma unroll
        for (int kk = 0; kk < 4; ++kk) {
            #pragma unroll
            for (int ng = 0; ng < 4; ++ng) {
                uint32_t b0, b1, b2, b3;
                ldm_x4t(b0, b1, b2, b3,
                        vb_ + (uint32_t)(kk * 16) * VSTR + vOff + (uint32_t)(ng * 16) * 2);
                mma16816(ctxa[ng * 2 + 0], pf[kk][0], pf[kk][1], pf[kk][2], pf[kk][3], b0, b1);
                mma16816(ctxa[ng * 2 + 1], pf[kk][0], pf[kk][1], pf[kk][2], pf[kk][3], b2, b3);
            }
        }
    }

    // ---- final l reduction across the quad (lanes sharing a row) ----
    #pragma unroll
    for (int o = 1; o < 4; o <<= 1) {
        l[0] += __shfl_xor_sync(0xffffffffu, l[0], o);
        l[1] += __shfl_xor_sync(0xffffffffu, l[1], o);
    }
    const float inv0 = 1.f / l[0];
    const float inv1 = 1.f / l[1];

    // ---- epilogue: write ctx directly as split bf16 [hi | lo | hi] ----
    __nv_bfloat16* C0 = ctx3 + (size_t)(b * LQc + q0 + wr + r0) * K3 + h * HDc;
    __nv_bfloat16* C1 = C0 + 8 * (size_t)K3;
    #pragma unroll
    for (int nf = 0; nf < 8; ++nf) {
        const int col = nf * 8 + c2;
        float v00 = ctxa[nf][0] * inv0, v01 = ctxa[nf][1] * inv0;
        float v10 = ctxa[nf][2] * inv1, v11 = ctxa[nf][3] * inv1;
        {
            __nv_bfloat16 h0 = __float2bfloat16(v00);
            __nv_bfloat16 h1 = __float2bfloat16(v01);
            uint32_t hp = (uint32_t)__bfloat16_as_ushort(h0)
                        | ((uint32_t)__bfloat16_as_ushort(h1) << 16);
            uint32_t lp = packbf2(v00 - __bfloat162float(h0), v01 - __bfloat162float(h1));
            *reinterpret_cast<uint32_t*>(C0 + col)        = hp;
            *reinterpret_cast<uint32_t*>(C0 + col + Hc)   = lp;
            *reinterpret_cast<uint32_t*>(C0 + col + 2*Hc) = hp;
        }
        {
            __nv_bfloat16 h0 = __float2bfloat16(v10);
            __nv_bfloat16 h1 = __float2bfloat16(v11);
            uint32_t hp = (uint32_t)__bfloat16_as_ushort(h0)
                        | ((uint32_t)__bfloat16_as_ushort(h1) << 16);
            uint32_t lp = packbf2(v10 - __bfloat162float(h0), v11 - __bfloat162float(h1));
            *reinterpret_cast<uint32_t*>(C1 + col)        = hp;
            *reinterpret_cast<uint32_t*>(C1 + col + Hc)   = lp;
            *reinterpret_cast<uint32_t*>(C1 + col + 2*Hc) = hp;
        }
    }
}

// ===========================================================================
// LayerNorm
// ===========================================================================
__global__ __launch_bounds__(256) void ln_kernel(
    const float* __restrict__ y, const float* __restrict__ w,
    const float* __restrict__ bvec, float* __restrict__ out)
{
    __shared__ float sh[8];
    const int row = blockIdx.x;
    const int tid = threadIdx.x;
    const float* yr = y + (size_t)row * Hc;

    float v[4];
    float s = 0.f;
    #pragma unroll
    for (int i = 0; i < 4; i++) { v[i] = yr[tid + i * 256]; s += v[i]; }
    #pragma unroll
    for (int o = 16; o > 0; o >>= 1) s += __shfl_xor_sync(0xffffffffu, s, o);
    if ((tid & 31) == 0) sh[tid >> 5] = s;
    __syncthreads();
    float mu = (sh[0] + sh[1] + sh[2] + sh[3] + sh[4] + sh[5] + sh[6] + sh[7])
               * (1.f / Hc);
    __syncthreads();

    float s2 = 0.f;
    #pragma unroll
    for (int i = 0; i < 4; i++) { float d = v[i] - mu; s2 += d * d; }
    #pragma unroll
    for (int o = 16; o > 0; o >>= 1) s2 += __shfl_xor_sync(0xffffffffu, s2, o);
    if ((tid & 31) == 0) sh[tid >> 5] = s2;
    __syncthreads();
    float var = (sh[0] + sh[1] + sh[2] + sh[3] + sh[4] + sh[5] + sh[6] + sh[7])
                * (1.f / Hc);
    float inv = rsqrtf(var + 1e-12f);

    #pragma unroll
    for (int i = 0; i < 4; i++) {
        int c = tid + i * 256;
        out[(size_t)row * Hc + c] = (v[i] - mu) * inv * w[c] + bvec[c];
    }
}

// ===========================================================================
extern "C" void kernel_launch(void* const* d_in, const int* in_sizes, int n_in,
                              void* d_out, int out_size)
{
    const float* hs  = (const float*)d_in[0];
    const float* ehs = (const float*)d_in[1];
    const int*   msk = (const int*)  d_in[2];
    const float* q_w = (const float*)d_in[3];
    const float* q_b = (const float*)d_in[4];
    const float* k_w = (const float*)d_in[5];
    const float* k_b = (const float*)d_in[6];
    const float* v_w = (const float*)d_in[7];
    const float* v_b = (const float*)d_in[8];
    const float* o_w = (const float*)d_in[9];
    const float* o_b = (const float*)d_in[10];
    const float* lw  = (const float*)d_in[11];
    const float* lb  = (const float*)d_in[12];

    float* out    = (float*)d_out;
    float* scores = out + (size_t)Bc * LQc * Hc;

    float* Y;
    cudaGetSymbolAddress((void**)&Y, g_y);

    __nv_bfloat16 *hs3, *ehs3, *ctx3, *qw3, *kw3, *vw3, *ow3;
    __nv_bfloat16 *Qh, *Ql, *Kh, *Kl, *Vh;
    cudaGetSymbolAddress((void**)&hs3,  g_hs3);
    cudaGetSymbolAddress((void**)&ehs3, g_ehs3);
    cudaGetSymbolAddress((void**)&ctx3, g_ctx3);
    cudaGetSymbolAddress((void**)&qw3,  g_qw3);
    cudaGetSymbolAddress((void**)&kw3,  g_kw3);
    cudaGetSymbolAddress((void**)&vw3,  g_vw3);
    cudaGetSymbolAddress((void**)&ow3,  g_ow3);
    cudaGetSymbolAddress((void**)&Qh,   g_Qhi);
    cudaGetSymbolAddress((void**)&Ql,   g_Qlo);
    cudaGetSymbolAddress((void**)&Kh,   g_Khi);
    cudaGetSymbolAddress((void**)&Kl,   g_Klo);
    cudaGetSymbolAddress((void**)&Vh,   g_Vhi);

    const int nHS  = Bc * LQc * Hc;
    const int nEHS = Bc * LKVc * Hc;
    const int nW   = Hc * Hc;

    dim3 blk(256);

    split3<<<nHS  / 4 / 256, blk>>>(hs,  hs3,  nHS  / 4, 0);
    split3<<<nEHS / 4 / 256, blk>>>(ehs, ehs3, nEHS / 4, 0);
    split3<<<nW   / 4 / 256, blk>>>(q_w, qw3,  nW / 4, 1);
    split3<<<nW   / 4 / 256, blk>>>(k_w, kw3,  nW / 4, 1);
    split3<<<nW   / 4 / 256, blk>>>(v_w, vw3,  nW / 4, 1);
    split3<<<nW   / 4 / 256, blk>>>(o_w, ow3,  nW / 4, 1);

    cudaFuncSetAttribute(gemm_mma<48>, cudaFuncAttributeMaxDynamicSharedMemorySize, GSMEM);
    cudaFuncSetAttribute(gemm_mma<16>, cudaFuncAttributeMaxDynamicSharedMemorySize, GSMEM);
    // Q/K projections: split precision, emit bf16 hi/lo
    gemm_mma<48><<<dim3(Hc / 128, (Bc * LQc)  / 128), blk, GSMEM>>>(
        hs3,  qw3, q_b, nullptr, nullptr, Qh, Ql, 1);
    gemm_mma<48><<<dim3(Hc / 128, (Bc * LKVc) / 128), blk, GSMEM>>>(
        ehs3, kw3, k_b, nullptr, nullptr, Kh, Kl, 1);
    // V projection: plain bf16 (hi x hi)
    gemm_mma<16><<<dim3(Hc / 128, (Bc * LKVc) / 128), blk, GSMEM>>>(
        ehs3, vw3, v_b, nullptr, nullptr, Vh, nullptr, 2);

    cudaFuncSetAttribute(attn_mma, cudaFuncAttributeMaxDynamicSharedMemorySize, ASMEM);
    attn_mma<<<dim3(LQc / 128, NHc, Bc), blk, ASMEM>>>(
        Qh, Ql, Kh, Kl, Vh, msk, scores, ctx3);

    // O projection (reads split ctx3 directly; bias + residual fused), then LN
    gemm_mma<48><<<dim3(Hc / 128, (Bc * LQc) / 128), blk, GSMEM>>>(
        ctx3, ow3, o_b, hs, Y, nullptr, nullptr, 0);
    ln_kernel<<<Bc * LQc, blk>>>(Y, lw, lb, out);
}